// round 14
// baseline (speedup 1.0000x reference)
#include <cuda_runtime.h>
#include <cuda_bf16.h>
#include <cstdint>

#define BATCH 32
#define NN    512
#define MM    512
#define DD    64
#define LDIAG 1023           // N + M - 1 anti-diagonals
#define BIGF  1e30f
#define LOG2E 1.4426950408889634f
#define LN2   0.6931471805599453f

// Scratch: distance * log2(e) in diagonal layout:
//   g_Ddiag[b][d][r] = LOG2E * D[b][r][d-r],  d = r + j (0-based), r = row.
// 32 * 1023 * 512 * 4B = ~64 MB. Invalid slots never read by the DP.
__device__ float g_Ddiag[(size_t)BATCH * LDIAG * NN];

// ---------------------------------------------------------------------------
// Kernel 1: D for a 128x128 tile, 8x8 register microtile per thread,
// k-major (transposed) smem, norms folded, diagonal-layout coalesced store.
// Stores D * LOG2E so the DP runs natively in the log2 domain.
// ---------------------------------------------------------------------------
#define DIST_SMEM_BYTES (16896 * 4)

__global__ __launch_bounds__(256) void dist_kernel(const float* __restrict__ X,
                                                   const float* __restrict__ Y) {
    extern __shared__ float sm[];
    float* Xs  = sm;                 // [64][128] k-major
    float* Ys  = sm + 64 * 128;      // [64][128] k-major
    float* Dt  = sm;                 // [128][130] (reuses Xs/Ys after barrier)
    float* x2s = sm + 16640;
    float* y2s = x2s + 128;

    const int b  = blockIdx.z;
    const int i0 = blockIdx.y * 128;
    const int j0 = blockIdx.x * 128;
    const int tid = threadIdx.x;

    const float* Xg = X + ((size_t)b * NN + i0) * DD;
    const float* Yg = Y + ((size_t)b * MM + j0) * DD;

    for (int l = tid; l < 128 * 16; l += 256) {
        int kq = l >> 7;
        int r  = l & 127;
        float4 vx = *(const float4*)(Xg + (size_t)r * DD + kq * 4);
        float4 vy = *(const float4*)(Yg + (size_t)r * DD + kq * 4);
        Xs[(kq * 4 + 0) * 128 + r] = vx.x;
        Xs[(kq * 4 + 1) * 128 + r] = vx.y;
        Xs[(kq * 4 + 2) * 128 + r] = vx.z;
        Xs[(kq * 4 + 3) * 128 + r] = vx.w;
        Ys[(kq * 4 + 0) * 128 + r] = vy.x;
        Ys[(kq * 4 + 1) * 128 + r] = vy.y;
        Ys[(kq * 4 + 2) * 128 + r] = vy.z;
        Ys[(kq * 4 + 3) * 128 + r] = vy.w;
    }
    __syncthreads();

    if (tid < 128) {
        float s = 0.0f;
        #pragma unroll 8
        for (int k = 0; k < 64; ++k) { float v = Xs[k * 128 + tid]; s += v * v; }
        x2s[tid] = s;
    } else {
        int c = tid - 128;
        float s = 0.0f;
        #pragma unroll 8
        for (int k = 0; k < 64; ++k) { float v = Ys[k * 128 + c]; s += v * v; }
        y2s[c] = s;
    }

    const int tx = tid & 15, ty = tid >> 4;
    float acc[8][8];
    #pragma unroll
    for (int i = 0; i < 8; i++)
        #pragma unroll
        for (int j = 0; j < 8; j++) acc[i][j] = 0.0f;

    const float* xp = Xs + ty * 8;
    const float* yp = Ys + tx * 8;
    #pragma unroll 4
    for (int k = 0; k < 64; ++k) {
        float4 a0 = *(const float4*)(xp + k * 128);
        float4 a1 = *(const float4*)(xp + k * 128 + 4);
        float4 b0 = *(const float4*)(yp + k * 128);
        float4 b1 = *(const float4*)(yp + k * 128 + 4);
        float av[8] = {a0.x, a0.y, a0.z, a0.w, a1.x, a1.y, a1.z, a1.w};
        float bv[8] = {b0.x, b0.y, b0.z, b0.w, b1.x, b1.y, b1.z, b1.w};
        #pragma unroll
        for (int i = 0; i < 8; i++)
            #pragma unroll
            for (int j = 0; j < 8; j++)
                acc[i][j] += av[i] * bv[j];
    }
    __syncthreads();

    #pragma unroll
    for (int i = 0; i < 8; i++) {
        float xi = x2s[ty * 8 + i];
        #pragma unroll
        for (int j = 0; j < 8; j++)
            Dt[(ty * 8 + i) * 130 + tx * 8 + j] =
                fmaf(-2.0f, acc[i][j], xi + y2s[tx * 8 + j]);
    }
    __syncthreads();

    float* outb = g_Ddiag + (size_t)b * LDIAG * NN;
    const int g  = tid >> 7;
    const int lt = tid & 127;
    for (int t = g; t < 255; t += 2) {
        int lo = t - 127; if (lo < 0) lo = 0;
        int hi = t < 127 ? t : 127;
        int il = lo + lt;
        if (il <= hi)
            outb[(size_t)(i0 + j0 + t) * NN + (i0 + il)] =
                Dt[il * 130 + (t - il)] * LOG2E;
    }
}

// ---------------------------------------------------------------------------
// Kernel 2: soft-DTW DP, block-skewed wavefront (R13 structure), slimmed:
//  - single SHFL per cell (nb2 is a register rename of old nb1)
//  - warp-0 row-boundary handling specialized out of warps 1..15
//  - unified nb1 SEL
// One CTA per batch, 512 threads; warp w owns rows 32w..32w+31. Block (w,i)
// = 8 diagonals; interval tau runs block tau-w per warp; one __syncthreads
// per interval. Seam = 8 floats, parity double-buffered, barrier-ordered.
// D via per-thread cp.async double-buffered blocks (wait_group 1).
// Softmin in log2 domain: mn - lg2(1 + ex2(mn-mid) + ex2(mn-mx)).
// ---------------------------------------------------------------------------
__device__ __forceinline__ uint32_t smem_u32(const void* p) {
    uint32_t a;
    asm("{ .reg .u64 t; cvta.to.shared.u64 t, %1; cvt.u32.u64 %0, t; }"
        : "=r"(a) : "l"(p));
    return a;
}
__device__ __forceinline__ float ex2f(float x) {
    float r; asm("ex2.approx.f32 %0, %1;" : "=f"(r) : "f"(x)); return r;
}
__device__ __forceinline__ float lg2f(float x) {
    float r; asm("lg2.approx.f32 %0, %1;" : "=f"(r) : "f"(x)); return r;
}

#define NBLK   128            // 1024 diagonals = 1023 real + 1 pad
#define NINTV  (NBLK + 15)    // skewed intervals

// One 8-diagonal block for one warp. W0: this warp contains row 0.
// LAST: this warp is warp 15 (no downstream seam).
template<bool W0, bool LAST>
__device__ __forceinline__ void do_block(
    int i, int t, int lane,
    const float* ringblk,            // &ring[par][0][0], stride 512 per k
    float* seam_out,                 // &seam[w][par][0]   (unused if LAST)
    const float* seam_in,            // &seam[w-1][par][0] (unused if W0)
    float& p1, float& p2, float& nb1, float& nb2)
{
    float s[8];
    if (!W0 && lane == 0) {
        float4 lo4 = *(const float4*)(seam_in);
        float4 hi4 = *(const float4*)(seam_in + 4);
        s[0] = lo4.x; s[1] = lo4.y; s[2] = lo4.z; s[3] = lo4.w;
        s[4] = hi4.x; s[5] = hi4.y; s[6] = hi4.z; s[7] = hi4.w;
    }
    #pragma unroll
    for (int k = 0; k < 8; ++k) {
        const int d = i * 8 + k;
        float Dv = ringblk[k * 512 + t];

        float a = nb2, bb = nb1, c = p1;
        if (W0) {
            if (t == 0) a = (d == 0) ? 0.0f : BIGF;   // virtual row -1 boundary
        }
        float lo_ = fminf(a, bb), hi_ = fmaxf(a, bb);
        float mn  = fminf(lo_, c);
        float mid = fminf(hi_, fmaxf(lo_, c));
        float mx  = fmaxf(hi_, c);
        float sum = 1.0f + ex2f(mn - mid) + ex2f(mn - mx);
        float cur = Dv + mn - lg2f(sum);
        if ((unsigned)(d - t) >= (unsigned)MM) cur = BIGF;   // j out of [0,M)

        float u1 = __shfl_up_sync(0xffffffffu, cur, 1);
        if (!LAST && lane == 31) seam_out[k] = cur;

        p2  = p1;  p1  = cur;
        nb2 = nb1;                                   // = row t-1 @ d-1 (rename)
        nb1 = (lane == 0) ? (W0 ? BIGF : s[k]) : u1; // = row t-1 @ d
    }
}

__global__ __launch_bounds__(512) void dp_kernel(float* __restrict__ outp) {
    __shared__ float ring[2][8][512];   // [buf][k][thread]: per-thread-private D
    __shared__ float seam[15][2][8];    // [producer warp][block parity][k]

    const int t    = threadIdx.x;
    const int b    = blockIdx.x;
    const int lane = t & 31;
    const int w    = t >> 5;

    const float* P = g_Ddiag + (size_t)b * LDIAG * NN;
    const uint32_t ring_t = smem_u32(&ring[0][0][0]) + (uint32_t)t * 4u;

    // Prologue: prefetch blocks 0 and 1 (one commit group per block).
    #pragma unroll
    for (int blk = 0; blk < 2; ++blk) {
        #pragma unroll
        for (int k = 0; k < 8; ++k) {
            const float* gp = P + (size_t)(blk * 8 + k) * 512 + t;
            asm volatile("cp.async.ca.shared.global [%0], [%1], 4;\n"
                         :: "r"(ring_t + (uint32_t)(blk * 8 + k) * 2048u), "l"(gp)
                         : "memory");
        }
        asm volatile("cp.async.commit_group;\n" ::: "memory");
    }

    float p1 = BIGF, p2 = BIGF;      // this row at d-1, d-2
    float nb1 = BIGF, nb2 = BIGF;    // row t-1 at d-1, d-2
    __syncthreads();

    for (int tau = 0; tau < NINTV; ++tau) {
        const int i = tau - w;       // this warp's block index this interval
        if ((unsigned)i < (unsigned)NBLK) {
            const int par = i & 1;

            // Block i's D data (group issued 2 blocks ago) must be complete.
            asm volatile("cp.async.wait_group 1;\n" ::: "memory");

            const float* ringblk  = &ring[par][0][0];
            float*       seam_out = &seam[w][par][0];          // w<15 only
            const float* seam_in  = &seam[(w == 0 ? 0 : w - 1)][par][0];

            if (w == 0)
                do_block<true,  false>(i, t, lane, ringblk, seam_out, seam_in,
                                       p1, p2, nb1, nb2);
            else if (w == 15)
                do_block<false, true >(i, t, lane, ringblk, seam_out, seam_in,
                                       p1, p2, nb1, nb2);
            else
                do_block<false, false>(i, t, lane, ringblk, seam_out, seam_in,
                                       p1, p2, nb1, nb2);

            // Prefetch block i+2 into buffer par (just fully consumed).
            #pragma unroll
            for (int k = 0; k < 8; ++k) {
                int d = (i + 2) * 8 + k; if (d > LDIAG - 1) d = LDIAG - 1;
                const float* gp = P + (size_t)d * 512 + t;
                asm volatile("cp.async.ca.shared.global [%0], [%1], 4;\n"
                             :: "r"(ring_t + (uint32_t)(par * 8 + k) * 2048u), "l"(gp)
                             : "memory");
            }
            asm volatile("cp.async.commit_group;\n" ::: "memory");
        }
        __syncthreads();   // orders seam writes (tau) before reads (tau+1)
    }

    // Thread 511: p2 = cur@1022 = R[N][M] (log2 units); diag 1023 is padding.
    if (t == NN - 1) outp[b] = p2 * LN2;
}

// ---------------------------------------------------------------------------
extern "C" void kernel_launch(void* const* d_in, const int* in_sizes, int n_in,
                              void* d_out, int out_size) {
    const float* X = (const float*)d_in[0];   // [32, 512, 64]
    const float* Y = (const float*)d_in[1];   // [32, 512, 64]
    float* out = (float*)d_out;               // [32]

    cudaFuncSetAttribute(dist_kernel, cudaFuncAttributeMaxDynamicSharedMemorySize,
                         DIST_SMEM_BYTES);

    dist_kernel<<<dim3(MM / 128, NN / 128, BATCH), 256, DIST_SMEM_BYTES>>>(X, Y);
    dp_kernel<<<BATCH, 512>>>(out);
}

// round 15
// speedup vs baseline: 1.0123x; 1.0123x over previous
#include <cuda_runtime.h>
#include <cuda_bf16.h>
#include <cstdint>

#define BATCH 32
#define NN    512
#define MM    512
#define DD    64
#define LDIAG 1023           // N + M - 1 anti-diagonals
#define BIGF  1e30f
#define LOG2E 1.4426950408889634f
#define LN2   0.6931471805599453f

// Scratch: distance * log2(e) in diagonal layout:
//   g_Ddiag[b][d][r] = LOG2E * D[b][r][d-r],  d = r + j (0-based), r = row.
// 32 * 1023 * 512 * 4B = ~64 MB. Invalid slots never read by the DP.
__device__ float g_Ddiag[(size_t)BATCH * LDIAG * NN];

// ---------------------------------------------------------------------------
// Kernel 1: D for a 128x128 tile, 8x8 register microtile per thread,
// k-major (transposed) smem, norms folded, diagonal-layout coalesced store.
// Stores D * LOG2E so the DP runs natively in the log2 domain.
// ---------------------------------------------------------------------------
#define DIST_SMEM_BYTES (16896 * 4)

__global__ __launch_bounds__(256) void dist_kernel(const float* __restrict__ X,
                                                   const float* __restrict__ Y) {
    extern __shared__ float sm[];
    float* Xs  = sm;                 // [64][128] k-major
    float* Ys  = sm + 64 * 128;      // [64][128] k-major
    float* Dt  = sm;                 // [128][130] (reuses Xs/Ys after barrier)
    float* x2s = sm + 16640;
    float* y2s = x2s + 128;

    const int b  = blockIdx.z;
    const int i0 = blockIdx.y * 128;
    const int j0 = blockIdx.x * 128;
    const int tid = threadIdx.x;

    const float* Xg = X + ((size_t)b * NN + i0) * DD;
    const float* Yg = Y + ((size_t)b * MM + j0) * DD;

    for (int l = tid; l < 128 * 16; l += 256) {
        int kq = l >> 7;
        int r  = l & 127;
        float4 vx = *(const float4*)(Xg + (size_t)r * DD + kq * 4);
        float4 vy = *(const float4*)(Yg + (size_t)r * DD + kq * 4);
        Xs[(kq * 4 + 0) * 128 + r] = vx.x;
        Xs[(kq * 4 + 1) * 128 + r] = vx.y;
        Xs[(kq * 4 + 2) * 128 + r] = vx.z;
        Xs[(kq * 4 + 3) * 128 + r] = vx.w;
        Ys[(kq * 4 + 0) * 128 + r] = vy.x;
        Ys[(kq * 4 + 1) * 128 + r] = vy.y;
        Ys[(kq * 4 + 2) * 128 + r] = vy.z;
        Ys[(kq * 4 + 3) * 128 + r] = vy.w;
    }
    __syncthreads();

    if (tid < 128) {
        float s = 0.0f;
        #pragma unroll 8
        for (int k = 0; k < 64; ++k) { float v = Xs[k * 128 + tid]; s += v * v; }
        x2s[tid] = s;
    } else {
        int c = tid - 128;
        float s = 0.0f;
        #pragma unroll 8
        for (int k = 0; k < 64; ++k) { float v = Ys[k * 128 + c]; s += v * v; }
        y2s[c] = s;
    }

    const int tx = tid & 15, ty = tid >> 4;
    float acc[8][8];
    #pragma unroll
    for (int i = 0; i < 8; i++)
        #pragma unroll
        for (int j = 0; j < 8; j++) acc[i][j] = 0.0f;

    const float* xp = Xs + ty * 8;
    const float* yp = Ys + tx * 8;
    #pragma unroll 4
    for (int k = 0; k < 64; ++k) {
        float4 a0 = *(const float4*)(xp + k * 128);
        float4 a1 = *(const float4*)(xp + k * 128 + 4);
        float4 b0 = *(const float4*)(yp + k * 128);
        float4 b1 = *(const float4*)(yp + k * 128 + 4);
        float av[8] = {a0.x, a0.y, a0.z, a0.w, a1.x, a1.y, a1.z, a1.w};
        float bv[8] = {b0.x, b0.y, b0.z, b0.w, b1.x, b1.y, b1.z, b1.w};
        #pragma unroll
        for (int i = 0; i < 8; i++)
            #pragma unroll
            for (int j = 0; j < 8; j++)
                acc[i][j] += av[i] * bv[j];
    }
    __syncthreads();

    #pragma unroll
    for (int i = 0; i < 8; i++) {
        float xi = x2s[ty * 8 + i];
        #pragma unroll
        for (int j = 0; j < 8; j++)
            Dt[(ty * 8 + i) * 130 + tx * 8 + j] =
                fmaf(-2.0f, acc[i][j], xi + y2s[tx * 8 + j]);
    }
    __syncthreads();

    float* outb = g_Ddiag + (size_t)b * LDIAG * NN;
    const int g  = tid >> 7;
    const int lt = tid & 127;
    for (int t = g; t < 255; t += 2) {
        int lo = t - 127; if (lo < 0) lo = 0;
        int hi = t < 127 ? t : 127;
        int il = lo + lt;
        if (il <= hi)
            outb[(size_t)(i0 + j0 + t) * NN + (i0 + il)] =
                Dt[il * 130 + (t - il)] * LOG2E;
    }
}

// ---------------------------------------------------------------------------
// Kernel 2: soft-DTW DP, block-skewed wavefront with EXPLICIT dead-block
// skipping. One CTA per batch, 512 threads; warp w owns rows 32w..32w+31
// (1 row/thread, register state). Block (w,i) = 8 diagonals; interval tau
// runs block tau-w; one __syncthreads per interval. Seam = 8 floats, parity
// double-buffered, barrier-ordered. Dead blocks (warp's rows entirely outside
// the band) take a uniform early-out (~4 insts vs ~200). Per-cell validity
// stays in branch form so boundary blocks predicate off the MUFU chain.
// D via per-thread cp.async double-buffered blocks (wait_group 1), uniform
// across skip/live blocks. Softmin in log2 domain (3 MUFU/cell).
// ---------------------------------------------------------------------------
__device__ __forceinline__ uint32_t smem_u32(const void* p) {
    uint32_t a;
    asm("{ .reg .u64 t; cvta.to.shared.u64 t, %1; cvt.u32.u64 %0, t; }"
        : "=r"(a) : "l"(p));
    return a;
}
__device__ __forceinline__ float ex2f(float x) {
    float r; asm("ex2.approx.f32 %0, %1;" : "=f"(r) : "f"(x)); return r;
}
__device__ __forceinline__ float lg2f(float x) {
    float r; asm("lg2.approx.f32 %0, %1;" : "=f"(r) : "f"(x)); return r;
}

#define NBLK   128            // 1024 diagonals = 1023 real + 1 pad
#define NINTV  (NBLK + 15)    // skewed intervals

// One 8-diagonal block for one warp. W0: warp contains row 0 (no upstream).
// LAST: warp 15 (no downstream seam).
template<bool W0, bool LAST>
__device__ __forceinline__ void do_block(
    int i, int t, int lane, int wbase,
    const float* ringblk,            // &ring[par][0][0], stride 512 per k
    float* seam_out,                 // &seam[w][par][0]   (unused if LAST)
    const float* seam_in,            // &seam[w-1][par][0] (unused if W0)
    float& p1, float& p2, float& nb1, float& nb2)
{
    const int d0 = i * 8;

    if (!W0) {
        // Dead-early: even lane 0 (smallest row) has d < t all block.
        if (d0 + 7 < wbase) {
            // Keep the seam window current so the first live block sees
            // nb1 = row wbase-1 @ d0+7, nb2 = @ d0+6. (Producer of the last
            // dead-early block is always live, so these are fresh.)
            if (lane == 0) { nb2 = seam_in[6]; nb1 = seam_in[7]; }
            return;
        }
    }
    // Dead-late: even lane 31 (largest row) has d - t > M-1 all block.
    if (d0 > wbase + 31 + (MM - 1)) return;

    float s[8];
    if (!W0 && lane == 0) {
        float4 lo4 = *(const float4*)(seam_in);
        float4 hi4 = *(const float4*)(seam_in + 4);
        s[0] = lo4.x; s[1] = lo4.y; s[2] = lo4.z; s[3] = lo4.w;
        s[4] = hi4.x; s[5] = hi4.y; s[6] = hi4.z; s[7] = hi4.w;
    }

    const int jb = d0 - t;           // j of cell k is jb + k
    #pragma unroll
    for (int k = 0; k < 8; ++k) {
        float cur = BIGF;
        if ((unsigned)(jb + k) < (unsigned)MM) {     // valid cell
            float Dv = ringblk[k * 512 + t];
            float a = nb2, bb = nb1, c = p1;
            if (W0) {
                if (t == 0) a = (d0 + k == 0) ? 0.0f : BIGF;  // row -1 boundary
            }
            float lo_ = fminf(a, bb), hi_ = fmaxf(a, bb);
            float mn  = fminf(lo_, c);
            float mid = fminf(hi_, fmaxf(lo_, c));
            float mx  = fmaxf(hi_, c);
            float sum = 1.0f + ex2f(mn - mid) + ex2f(mn - mx);
            cur = Dv + mn - lg2f(sum);
        }

        float u1 = __shfl_up_sync(0xffffffffu, cur, 1);
        if (!LAST && lane == 31) seam_out[k] = cur;

        p2  = p1;  p1 = cur;
        if (lane == 0) { nb2 = nb1; nb1 = W0 ? BIGF : s[k]; }
        else           { nb2 = nb1; nb1 = u1; }
    }
}

__global__ __launch_bounds__(512) void dp_kernel(float* __restrict__ outp) {
    __shared__ float ring[2][8][512];   // [buf][k][thread]: per-thread-private D
    __shared__ float seam[15][2][8];    // [producer warp][block parity][k]

    const int t    = threadIdx.x;
    const int b    = blockIdx.x;
    const int lane = t & 31;
    const int w    = t >> 5;
    const int wbase = w << 5;

    const float* P = g_Ddiag + (size_t)b * LDIAG * NN;
    const uint32_t ring_t = smem_u32(&ring[0][0][0]) + (uint32_t)t * 4u;

    // Prologue: prefetch blocks 0 and 1 (one commit group per block).
    #pragma unroll
    for (int blk = 0; blk < 2; ++blk) {
        #pragma unroll
        for (int k = 0; k < 8; ++k) {
            const float* gp = P + (size_t)(blk * 8 + k) * 512 + t;
            asm volatile("cp.async.ca.shared.global [%0], [%1], 4;\n"
                         :: "r"(ring_t + (uint32_t)(blk * 8 + k) * 2048u), "l"(gp)
                         : "memory");
        }
        asm volatile("cp.async.commit_group;\n" ::: "memory");
    }

    float p1 = BIGF, p2 = BIGF;      // this row at d-1, d-2
    float nb1 = BIGF, nb2 = BIGF;    // row t-1 at d-1, d-2
    __syncthreads();

    for (int tau = 0; tau < NINTV; ++tau) {
        const int i = tau - w;       // this warp's block index this interval
        if ((unsigned)i < (unsigned)NBLK) {
            const int par = i & 1;

            // Block i's D data (group issued 2 blocks ago) must be complete.
            asm volatile("cp.async.wait_group 1;\n" ::: "memory");

            const float* ringblk  = &ring[par][0][0];
            float*       seam_out = &seam[w][par][0];            // w<15 only
            const float* seam_in  = &seam[(w == 0 ? 0 : w - 1)][par][0];

            if (w == 0)
                do_block<true,  false>(i, t, lane, wbase, ringblk, seam_out,
                                       seam_in, p1, p2, nb1, nb2);
            else if (w == 15)
                do_block<false, true >(i, t, lane, wbase, ringblk, seam_out,
                                       seam_in, p1, p2, nb1, nb2);
            else
                do_block<false, false>(i, t, lane, wbase, ringblk, seam_out,
                                       seam_in, p1, p2, nb1, nb2);

            // Prefetch block i+2 into buffer par (just fully consumed).
            #pragma unroll
            for (int k = 0; k < 8; ++k) {
                int d = (i + 2) * 8 + k; if (d > LDIAG - 1) d = LDIAG - 1;
                const float* gp = P + (size_t)d * 512 + t;
                asm volatile("cp.async.ca.shared.global [%0], [%1], 4;\n"
                             :: "r"(ring_t + (uint32_t)(par * 8 + k) * 2048u), "l"(gp)
                             : "memory");
            }
            asm volatile("cp.async.commit_group;\n" ::: "memory");
        }
        __syncthreads();   // orders seam writes (tau) before reads (tau+1)
    }

    // Thread 511: p2 = cur@1022 = R[N][M] (log2 units); diag 1023 is padding.
    if (t == NN - 1) outp[b] = p2 * LN2;
}

// ---------------------------------------------------------------------------
extern "C" void kernel_launch(void* const* d_in, const int* in_sizes, int n_in,
                              void* d_out, int out_size) {
    const float* X = (const float*)d_in[0];   // [32, 512, 64]
    const float* Y = (const float*)d_in[1];   // [32, 512, 64]
    float* out = (float*)d_out;               // [32]

    cudaFuncSetAttribute(dist_kernel, cudaFuncAttributeMaxDynamicSharedMemorySize,
                         DIST_SMEM_BYTES);

    dist_kernel<<<dim3(MM / 128, NN / 128, BATCH), 256, DIST_SMEM_BYTES>>>(X, Y);
    dp_kernel<<<BATCH, 512>>>(out);
}

// round 17
// speedup vs baseline: 1.2577x; 1.2423x over previous
#include <cuda_runtime.h>
#include <cuda_bf16.h>
#include <cstdint>

#define BATCH 32
#define NN    512
#define MM    512
#define DD    64
#define LDIAG 1023           // N + M - 1 anti-diagonals
#define BIGF  1e30f
#define LOG2E 1.4426950408889634f
#define LN2   0.6931471805599453f

// Scratch: distance * log2(e) in diagonal layout:
//   g_Ddiag[b][d][r] = LOG2E * D[b][r][d-r],  d = r + j (0-based), r = row.
// 32 * 1023 * 512 * 4B = ~64 MB. Invalid slots never read by the DP.
__device__ float g_Ddiag[(size_t)BATCH * LDIAG * NN];

// ---------------------------------------------------------------------------
// Kernel 1: D for a 128x128 tile, 8x8 register microtile per thread,
// k-major (transposed) smem, norms folded, diagonal-layout coalesced store.
// Stores D * LOG2E so the DP runs natively in the log2 domain.
// ---------------------------------------------------------------------------
#define DIST_SMEM_BYTES (16896 * 4)

__global__ __launch_bounds__(256) void dist_kernel(const float* __restrict__ X,
                                                   const float* __restrict__ Y) {
    extern __shared__ float sm[];
    float* Xs  = sm;                 // [64][128] k-major
    float* Ys  = sm + 64 * 128;      // [64][128] k-major
    float* Dt  = sm;                 // [128][130] (reuses Xs/Ys after barrier)
    float* x2s = sm + 16640;
    float* y2s = x2s + 128;

    const int b  = blockIdx.z;
    const int i0 = blockIdx.y * 128;
    const int j0 = blockIdx.x * 128;
    const int tid = threadIdx.x;

    const float* Xg = X + ((size_t)b * NN + i0) * DD;
    const float* Yg = Y + ((size_t)b * MM + j0) * DD;

    for (int l = tid; l < 128 * 16; l += 256) {
        int kq = l >> 7;
        int r  = l & 127;
        float4 vx = *(const float4*)(Xg + (size_t)r * DD + kq * 4);
        float4 vy = *(const float4*)(Yg + (size_t)r * DD + kq * 4);
        Xs[(kq * 4 + 0) * 128 + r] = vx.x;
        Xs[(kq * 4 + 1) * 128 + r] = vx.y;
        Xs[(kq * 4 + 2) * 128 + r] = vx.z;
        Xs[(kq * 4 + 3) * 128 + r] = vx.w;
        Ys[(kq * 4 + 0) * 128 + r] = vy.x;
        Ys[(kq * 4 + 1) * 128 + r] = vy.y;
        Ys[(kq * 4 + 2) * 128 + r] = vy.z;
        Ys[(kq * 4 + 3) * 128 + r] = vy.w;
    }
    __syncthreads();

    if (tid < 128) {
        float s = 0.0f;
        #pragma unroll 8
        for (int k = 0; k < 64; ++k) { float v = Xs[k * 128 + tid]; s += v * v; }
        x2s[tid] = s;
    } else {
        int c = tid - 128;
        float s = 0.0f;
        #pragma unroll 8
        for (int k = 0; k < 64; ++k) { float v = Ys[k * 128 + c]; s += v * v; }
        y2s[c] = s;
    }

    const int tx = tid & 15, ty = tid >> 4;
    float acc[8][8];
    #pragma unroll
    for (int i = 0; i < 8; i++)
        #pragma unroll
        for (int j = 0; j < 8; j++) acc[i][j] = 0.0f;

    const float* xp = Xs + ty * 8;
    const float* yp = Ys + tx * 8;
    #pragma unroll 4
    for (int k = 0; k < 64; ++k) {
        float4 a0 = *(const float4*)(xp + k * 128);
        float4 a1 = *(const float4*)(xp + k * 128 + 4);
        float4 b0 = *(const float4*)(yp + k * 128);
        float4 b1 = *(const float4*)(yp + k * 128 + 4);
        float av[8] = {a0.x, a0.y, a0.z, a0.w, a1.x, a1.y, a1.z, a1.w};
        float bv[8] = {b0.x, b0.y, b0.z, b0.w, b1.x, b1.y, b1.z, b1.w};
        #pragma unroll
        for (int i = 0; i < 8; i++)
            #pragma unroll
            for (int j = 0; j < 8; j++)
                acc[i][j] += av[i] * bv[j];
    }
    __syncthreads();

    #pragma unroll
    for (int i = 0; i < 8; i++) {
        float xi = x2s[ty * 8 + i];
        #pragma unroll
        for (int j = 0; j < 8; j++)
            Dt[(ty * 8 + i) * 130 + tx * 8 + j] =
                fmaf(-2.0f, acc[i][j], xi + y2s[tx * 8 + j]);
    }
    __syncthreads();

    float* outb = g_Ddiag + (size_t)b * LDIAG * NN;
    const int g  = tid >> 7;
    const int lt = tid & 127;
    for (int t = g; t < 255; t += 2) {
        int lo = t - 127; if (lo < 0) lo = 0;
        int hi = t < 127 ? t : 127;
        int il = lo + lt;
        if (il <= hi)
            outb[(size_t)(i0 + j0 + t) * NN + (i0 + il)] =
                Dt[il * 130 + (t - il)] * LOG2E;
    }
}

// ---------------------------------------------------------------------------
// Kernel 2: soft-DTW DP, block-skewed wavefront (R13 structure, verbatim,
// EXCEPT a 4-FMNMX softmin: only min + the two non-min values in any order
// are needed — mid/mx sorting was redundant).
// One CTA per batch, 512 threads; warp w owns rows 32w..32w+31 (1 row/thread,
// register state). Block (w, i) = 8 diagonals [8i, 8i+8). Interval tau runs
// block i = tau - w per warp; ONE __syncthreads per 8 diagonals; intra-block
// handoff is pure shfl; seam = 8 floats/block, parity double-buffered,
// barrier-ordered. D streams via per-thread cp.async double-buffered blocks
// (wait_group 1). Softmin in log2 domain: mn - lg2(1 + ex2(mn-v1) + ex2(mn-v2)).
// ---------------------------------------------------------------------------
__device__ __forceinline__ uint32_t smem_u32(const void* p) {
    uint32_t a;
    asm("{ .reg .u64 t; cvta.to.shared.u64 t, %1; cvt.u32.u64 %0, t; }"
        : "=r"(a) : "l"(p));
    return a;
}
__device__ __forceinline__ float ex2f(float x) {
    float r; asm("ex2.approx.f32 %0, %1;" : "=f"(r) : "f"(x)); return r;
}
__device__ __forceinline__ float lg2f(float x) {
    float r; asm("lg2.approx.f32 %0, %1;" : "=f"(r) : "f"(x)); return r;
}

#define NBLK   128            // 1024 diagonals = 1023 real + 1 pad
#define NINTV  (NBLK + 15)    // skewed intervals

__global__ __launch_bounds__(512) void dp_kernel(float* __restrict__ outp) {
    __shared__ float ring[2][8][512];   // [buf][k][thread]: per-thread-private D
    __shared__ float seam[15][2][8];    // [producer warp][block parity][k]

    const int t    = threadIdx.x;
    const int b    = blockIdx.x;
    const int lane = t & 31;
    const int w    = t >> 5;

    const float* P = g_Ddiag + (size_t)b * LDIAG * NN;
    const uint32_t ring_t = smem_u32(&ring[0][0][0]) + (uint32_t)t * 4u;

    // Prologue: prefetch blocks 0 and 1 (one commit group per block).
    #pragma unroll
    for (int blk = 0; blk < 2; ++blk) {
        #pragma unroll
        for (int k = 0; k < 8; ++k) {
            const float* gp = P + (size_t)(blk * 8 + k) * 512 + t;
            asm volatile("cp.async.ca.shared.global [%0], [%1], 4;\n"
                         :: "r"(ring_t + (uint32_t)(blk * 8 + k) * 2048u), "l"(gp)
                         : "memory");
        }
        asm volatile("cp.async.commit_group;\n" ::: "memory");
    }

    float p1 = BIGF, p2 = BIGF;      // this row at d-1, d-2
    float nb1 = BIGF, nb2 = BIGF;    // row t-1 at d-1, d-2
    __syncthreads();

    for (int tau = 0; tau < NINTV; ++tau) {
        const int i = tau - w;       // this warp's block index this interval
        if ((unsigned)i < (unsigned)NBLK) {
            const int par = i & 1;

            // Block i's D data (group issued 2 blocks ago) must be complete.
            asm volatile("cp.async.wait_group 1;\n" ::: "memory");

            // Lane 0 pulls the upstream seam for this block (written last
            // interval by warp w-1; ordered by the interval barrier).
            float s[8];
            if (lane == 0 && w > 0) {
                float4 lo4 = *(const float4*)&seam[w - 1][par][0];
                float4 hi4 = *(const float4*)&seam[w - 1][par][4];
                s[0] = lo4.x; s[1] = lo4.y; s[2] = lo4.z; s[3] = lo4.w;
                s[4] = hi4.x; s[5] = hi4.y; s[6] = hi4.z; s[7] = hi4.w;
            }

            #pragma unroll
            for (int k = 0; k < 8; ++k) {
                const int d = i * 8 + k;
                float Dv = ring[par][k][t];

                float a, bb;
                if (t == 0) { a = (d == 0) ? 0.0f : BIGF; bb = BIGF; }
                else        { a = nb2;                    bb = nb1; }
                float c = p1;

                float cur = BIGF;
                if ((unsigned)(d - t) < (unsigned)MM) {   // j = d - t in [0, M)
                    // 4-FMNMX softmin: mn = min3; {v1, hi_} = the two non-min
                    // values in arbitrary order (ordering irrelevant to the sum).
                    float lo_ = fminf(a, bb), hi_ = fmaxf(a, bb);
                    float mn  = fminf(lo_, c);
                    float v1  = fmaxf(lo_, c);
                    float sum = 1.0f + ex2f(mn - v1) + ex2f(mn - hi_);
                    cur = Dv + mn - lg2f(sum);
                }

                // Intra-warp handoff (p1 pre-rotation = this row @ d-1).
                float u1 = __shfl_up_sync(0xffffffffu, cur, 1);
                float u2 = __shfl_up_sync(0xffffffffu, p1, 1);

                // Downstream seam publish (consumed next interval).
                if (lane == 31 && w < 15) seam[w][par][k] = cur;

                p2 = p1; p1 = cur;
                if (lane == 0) { nb2 = nb1; nb1 = s[k]; }  // seam window shift
                else           { nb1 = u1;  nb2 = u2;  }
            }

            // Prefetch block i+2 into buffer par (just fully consumed).
            // Always issue (clamped source) to keep group counts uniform.
            #pragma unroll
            for (int k = 0; k < 8; ++k) {
                int d = (i + 2) * 8 + k; if (d > LDIAG - 1) d = LDIAG - 1;
                const float* gp = P + (size_t)d * 512 + t;
                asm volatile("cp.async.ca.shared.global [%0], [%1], 4;\n"
                             :: "r"(ring_t + (uint32_t)(par * 8 + k) * 2048u), "l"(gp)
                             : "memory");
            }
            asm volatile("cp.async.commit_group;\n" ::: "memory");
        }
        __syncthreads();   // orders seam writes (tau) before reads (tau+1)
    }

    // Thread 511: p2 = cur@1022 = R[N][M] (log2 units); diag 1023 is padding.
    if (t == NN - 1) outp[b] = p2 * LN2;
}

// ---------------------------------------------------------------------------
extern "C" void kernel_launch(void* const* d_in, const int* in_sizes, int n_in,
                              void* d_out, int out_size) {
    const float* X = (const float*)d_in[0];   // [32, 512, 64]
    const float* Y = (const float*)d_in[1];   // [32, 512, 64]
    float* out = (float*)d_out;               // [32]

    cudaFuncSetAttribute(dist_kernel, cudaFuncAttributeMaxDynamicSharedMemorySize,
                         DIST_SMEM_BYTES);

    dist_kernel<<<dim3(MM / 128, NN / 128, BATCH), 256, DIST_SMEM_BYTES>>>(X, Y);
    dp_kernel<<<BATCH, 512>>>(out);
}